// round 14
// baseline (speedup 1.0000x reference)
#include <cuda_runtime.h>
#include <cuda_fp16.h>

#define SQ      32
#define EMB     1024
#define NH      16
#define HD      64
#define PASTN   32768
#define TOT     32800
#define PCHUNK  448
#define NSPLITS 74       // 73 past splits + 1 new-token split
#define KCH     16
#define KCHLEN  64

// Scratch (allocation-free rule: __device__ globals)
__device__ float  g_qkv [SQ * 3 * EMB];
__device__ __half g_po  [NH * NSPLITS * SQ * HD];   // fp16 partial O
__device__ float  g_pml [NH * NSPLITS * SQ * 2];
__device__ float  g_a   [SQ * EMB];
__device__ float  g_pqkv[KCH * SQ * 3 * EMB];
__device__ float  g_pprj[KCH * SQ * EMB];

// ------------------------- helpers ----------------------------------------
__device__ __forceinline__ unsigned long long ffma2(
    unsigned long long a, unsigned long long b, unsigned long long c) {
    unsigned long long d;
    asm("fma.rn.f32x2 %0, %1, %2, %3;" : "=l"(d) : "l"(a), "l"(b), "l"(c));
    return d;
}
__device__ __forceinline__ unsigned long long pack2(float x, float y) {
    unsigned long long r;
    asm("mov.b64 %0, {%1, %2};" : "=l"(r) : "f"(x), "f"(y));
    return r;
}
__device__ __forceinline__ float2 unpack2(unsigned long long v) {
    float2 r;
    asm("mov.b64 {%0, %1}, %2;" : "=f"(r.x), "=f"(r.y) : "l"(v));
    return r;
}
__device__ __forceinline__ float ex2(float x) {
    float r;
    asm("ex2.approx.f32 %0, %1;" : "=f"(r) : "f"(x));
    return r;
}
__device__ __forceinline__ unsigned f2tf(float f) {
    unsigned u;
    asm("cvt.rna.tf32.f32 %0, %1;" : "=r"(u) : "f"(f));
    return u;
}
__device__ __forceinline__ void cp16(unsigned int saddr, const void* gptr) {
    asm volatile("cp.async.cg.shared.global [%0], [%1], 16;"
                 :: "r"(saddr), "l"(gptr));
}
__device__ __forceinline__ void mma_tf32(
    float* d, const unsigned* a, unsigned b0, unsigned b1) {
    asm volatile(
        "mma.sync.aligned.m16n8k8.row.col.f32.tf32.tf32.f32 "
        "{%0,%1,%2,%3}, {%4,%5,%6,%7}, {%8,%9}, {%0,%1,%2,%3};"
        : "+f"(d[0]), "+f"(d[1]), "+f"(d[2]), "+f"(d[3])
        : "r"(a[0]), "r"(a[1]), "r"(a[2]), "r"(a[3]), "r"(b0), "r"(b1));
}

// ---------------------------------------------------------------------------
// Split-K GEMM partial: part[kc][r][C] = x[r][k0:k0+64] @ w[k0:k0+64][C]
// grid (C/128, KCH), block 128.
// ---------------------------------------------------------------------------
__global__ __launch_bounds__(128) void gemm_part_kernel(
    const float* __restrict__ xsrc, const float* __restrict__ w,
    float* __restrict__ part, int C)
{
    __shared__ float xs_t[KCHLEN][36];
    const int c  = blockIdx.x * 128 + threadIdx.x;
    const int k0 = blockIdx.y * KCHLEN;

    {
        const int k = threadIdx.x & 63;
        const int j0 = (threadIdx.x >> 6) * 16;
#pragma unroll
        for (int jj = 0; jj < 16; jj++)
            xs_t[k][j0 + jj] = xsrc[(j0 + jj) * EMB + k0 + k];
    }
    __syncthreads();

    unsigned long long acc[16];
#pragma unroll
    for (int i = 0; i < 16; i++) acc[i] = 0ull;

#pragma unroll 16
    for (int k = 0; k < KCHLEN; k++) {
        const float wv = w[(size_t)(k0 + k) * C + c];
        const unsigned long long w2 = pack2(wv, wv);
#pragma unroll
        for (int r4 = 0; r4 < 8; r4++) {
            const ulonglong2 x4 = *(const ulonglong2*)&xs_t[k][r4 * 4];
            acc[r4 * 2]     = ffma2(x4.x, w2, acc[r4 * 2]);
            acc[r4 * 2 + 1] = ffma2(x4.y, w2, acc[r4 * 2 + 1]);
        }
    }

    float* p = part + (size_t)blockIdx.y * SQ * C + c;
#pragma unroll
    for (int i = 0; i < 16; i++) {
        const float2 v = unpack2(acc[i]);
        p[(size_t)(2 * i)     * C] = v.x;
        p[(size_t)(2 * i + 1) * C] = v.y;
    }
}

// ---------------------------------------------------------------------------
// Reduce qkv partials + bias -> g_qkv ; scatter new K/V rows into present tail
// ---------------------------------------------------------------------------
__global__ __launch_bounds__(256) void reduce_qkv_kernel(
    const float* __restrict__ b, float* __restrict__ dout)
{
    const int c = blockIdx.x * 256 + threadIdx.x;   // 0..3071
    const int r = blockIdx.y;
    float v0 = b[c], v1 = 0.f, v2 = 0.f, v3 = 0.f;
#pragma unroll
    for (int kc = 0; kc < KCH; kc += 4) {
        v0 += g_pqkv[((size_t)kc * SQ + r) * (3 * EMB) + c];
        v1 += g_pqkv[((size_t)(kc + 1) * SQ + r) * (3 * EMB) + c];
        v2 += g_pqkv[((size_t)(kc + 2) * SQ + r) * (3 * EMB) + c];
        v3 += g_pqkv[((size_t)(kc + 3) * SQ + r) * (3 * EMB) + c];
    }
    const float v = (v0 + v1) + (v2 + v3);
    g_qkv[r * 3 * EMB + c] = v;
    if (c >= EMB) {
        const int which = (c >= 2 * EMB) ? 1 : 0;   // 0=K, 1=V
        const int cc = c - EMB - which * EMB;
        const int h = cc / HD, d = cc % HD;
        dout[(size_t)SQ * EMB
             + ((size_t)which * NH + h) * (size_t)TOT * HD
             + (size_t)(PASTN + r) * HD + d] = v;
    }
}

// ---------------------------------------------------------------------------
// Attention via mma.sync tf32. CTA = 256 thr = 8 warps = 4 heads x 2 q-halves.
// grid (NSPLITS, 4) = 296 CTAs. Per-pair named barriers.
// SAFE pipeline: wait_group 0 -> pair-bar -> prefetch(i+1) -> compute.
// (Cross-warp smem reads are only valid because BOTH warps' waits precede
//  the shared barrier — do not reorder.)
// smem: K[4][2][16][68] + V[4][2][16][72] + Ps[8][16][20] = 80 KB.
// ---------------------------------------------------------------------------
#define KPAD 68
#define VPAD 72
#define K_OFF(head, buf) ((head) * 2176 + (buf) * 1088)
#define V_OFF(head, buf) (8704 + (head) * 2304 + (buf) * 1152)
#define P_OFF(warpid)    (17920 + (warpid) * 320)

__global__ __launch_bounds__(256) void attn_kernel(
    const float* __restrict__ past, float* __restrict__ dout)
{
    extern __shared__ float smem[];
    const int warp = threadIdx.x >> 5, lane = threadIdx.x & 31;
    const int head = warp >> 1, whalf = warp & 1;
    const int g = lane >> 2, t = lane & 3;
    const int sp = blockIdx.x;
    const int h  = blockIdx.y * 4 + head;

    const bool isnew = (sp == NSPLITS - 1);
    int t0, tend;
    if (isnew)                  { t0 = PASTN;       tend = TOT; }
    else if (sp == NSPLITS - 2) { t0 = sp * PCHUNK; tend = PASTN; }
    else                        { t0 = sp * PCHUNK; tend = t0 + PCHUNK; }
    const int nt = (tend - t0) >> 4;

    // ---- Q fragments: 8 k-steps x 4 regs (rows qlo=whalf*16+g, qhi=+8) ----
    const int qlo = whalf * 16 + g, qhi = qlo + 8;
    const float qc = 0.125f * 1.4426950408889634f;   // 1/sqrt(d) * log2(e)
    unsigned qf[32];
    {
        const float* qL = g_qkv + qlo * 3 * EMB + h * HD;
        const float* qH = g_qkv + qhi * 3 * EMB + h * HD;
#pragma unroll
        for (int ks = 0; ks < 8; ks++) {
            qf[ks * 4 + 0] = f2tf(qL[ks * 8 + t]     * qc);
            qf[ks * 4 + 1] = f2tf(qH[ks * 8 + t]     * qc);
            qf[ks * 4 + 2] = f2tf(qL[ks * 8 + t + 4] * qc);
            qf[ks * 4 + 3] = f2tf(qH[ks * 8 + t + 4] * qc);
        }
    }

    float of[8][4];
#pragma unroll
    for (int n = 0; n < 8; n++)
#pragma unroll
        for (int r = 0; r < 4; r++) of[n][r] = 0.f;
    float mlo = -1e30f, mhi = -1e30f, llo = 0.f, lhi = 0.f;

    float* presK = dout + SQ * EMB + (size_t)h * TOT * HD;
    float* presV = presK + (size_t)NH * TOT * HD;
    const float* srcK = isnew ? (presK + (size_t)t0 * HD)
                              : (past + ((size_t)h * PASTN + t0) * (size_t)HD);
    const float* srcV = isnew ? (presV + (size_t)t0 * HD)
                              : (past + ((size_t)(NH + h) * PASTN + t0) * (size_t)HD);

    float* Ps = smem + P_OFF(warp);
    unsigned* Pu = (unsigned*)Ps;
    const unsigned KsA = (unsigned)__cvta_generic_to_shared(smem);

    // ---- prefetch tile 0 (this warp loads its half of the head's rows) ----
#pragma unroll
    for (int r = 0; r < 4; r++) {
        const int idx = whalf * 128 + r * 32 + lane;   // 0..255 over pair
        const int row = idx >> 4, c4 = idx & 15;
        cp16(KsA + (unsigned)(K_OFF(head, 0) + row * KPAD + c4 * 4) * 4u,
             srcK + row * HD + c4 * 4);
        cp16(KsA + (unsigned)(V_OFF(head, 0) + row * VPAD + c4 * 4) * 4u,
             srcV + row * HD + c4 * 4);
    }
    asm volatile("cp.async.commit_group;");

    for (int i = 0; i < nt; i++) {
        const int buf = i & 1;
        // Tile i (K and V, this warp's halves) landed.
        asm volatile("cp.async.wait_group 0;");
        // Pair barrier: partner's halves also landed (its wait precedes its
        // barrier arrival), and partner finished compute i-1 -> the buffer
        // we prefetch into below is free.
        asm volatile("bar.sync %0, 64;" :: "r"(head + 1));

        if (i + 1 < nt) {
            const size_t gb = (size_t)(i + 1) * 16 * HD;
            const int bo = buf ^ 1;
#pragma unroll
            for (int r = 0; r < 4; r++) {
                const int idx = whalf * 128 + r * 32 + lane;
                const int row = idx >> 4, c4 = idx & 15;
                cp16(KsA + (unsigned)(K_OFF(head, bo) + row * KPAD + c4 * 4) * 4u,
                     srcK + gb + row * HD + c4 * 4);
                cp16(KsA + (unsigned)(V_OFF(head, bo) + row * VPAD + c4 * 4) * 4u,
                     srcV + gb + row * HD + c4 * 4);
            }
            asm volatile("cp.async.commit_group;");
        }

        const float* Kt = smem + K_OFF(head, buf);
        const float* Vt = smem + V_OFF(head, buf);
        const unsigned* Ku = (const unsigned*)Kt;
        const unsigned* Vu = (const unsigned*)Vt;
        const int tt = t0 + i * 16;

        // ---- QK: 2 n-tiles x 8 k-steps (2 acc chains each) ----
        float s[2][4];
#pragma unroll
        for (int n = 0; n < 2; n++) {
            float ca[4] = {0.f, 0.f, 0.f, 0.f};
            float cb[4] = {0.f, 0.f, 0.f, 0.f};
            const unsigned* Kr = Ku + (n * 8 + g) * KPAD + t;
#pragma unroll
            for (int ks = 0; ks < 4; ks++) {
                mma_tf32(ca, qf + 4 * ks,       Kr[ks * 8],       Kr[ks * 8 + 4]);
                mma_tf32(cb, qf + 4 * (ks + 4), Kr[(ks + 4) * 8], Kr[(ks + 4) * 8 + 4]);
            }
#pragma unroll
            for (int r = 0; r < 4; r++) s[n][r] = ca[r] + cb[r];
        }

        // ---- K copy-through (streaming stores; data landed pre-barrier) ----
        if (!isnew) {
#pragma unroll
            for (int r = 0; r < 4; r++) {
                const int idx = whalf * 128 + r * 32 + lane;
                const int row = idx >> 4, c4 = idx & 15;
                __stcs((float4*)&presK[(size_t)(tt + row) * HD + c4 * 4],
                       *(const float4*)(Kt + row * KPAD + c4 * 4));
            }
        }

        // ---- causal mask (new-token split only) ----
        if (isnew) {
            const int kb = i * 16;
#pragma unroll
            for (int n = 0; n < 2; n++) {
                const int col = n * 8 + 2 * t;
                if (kb + col     > qlo) s[n][0] = -1e30f;
                if (kb + col + 1 > qlo) s[n][1] = -1e30f;
                if (kb + col     > qhi) s[n][2] = -1e30f;
                if (kb + col + 1 > qhi) s[n][3] = -1e30f;
            }
        }

        // ---- online softmax (quad shfl reductions) ----
        float vlo = fmaxf(fmaxf(s[0][0], s[0][1]), fmaxf(s[1][0], s[1][1]));
        float vhi = fmaxf(fmaxf(s[0][2], s[0][3]), fmaxf(s[1][2], s[1][3]));
        vlo = fmaxf(vlo, __shfl_xor_sync(0xffffffffu, vlo, 1));
        vlo = fmaxf(vlo, __shfl_xor_sync(0xffffffffu, vlo, 2));
        vhi = fmaxf(vhi, __shfl_xor_sync(0xffffffffu, vhi, 1));
        vhi = fmaxf(vhi, __shfl_xor_sync(0xffffffffu, vhi, 2));
        const float nmlo = fmaxf(mlo, vlo), nmhi = fmaxf(mhi, vhi);
        const float allo = ex2(mlo - nmlo), alhi = ex2(mhi - nmhi);
        mlo = nmlo; mhi = nmhi;

        float p[2][4];
#pragma unroll
        for (int n = 0; n < 2; n++) {
            p[n][0] = ex2(s[n][0] - nmlo);
            p[n][1] = ex2(s[n][1] - nmlo);
            p[n][2] = ex2(s[n][2] - nmhi);
            p[n][3] = ex2(s[n][3] - nmhi);
        }
        float slo = (p[0][0] + p[0][1]) + (p[1][0] + p[1][1]);
        float shi = (p[0][2] + p[0][3]) + (p[1][2] + p[1][3]);
        slo += __shfl_xor_sync(0xffffffffu, slo, 1);
        slo += __shfl_xor_sync(0xffffffffu, slo, 2);
        shi += __shfl_xor_sync(0xffffffffu, shi, 1);
        shi += __shfl_xor_sync(0xffffffffu, shi, 2);
        llo = llo * allo + slo;
        lhi = lhi * alhi + shi;

#pragma unroll
        for (int n = 0; n < 8; n++) {
            of[n][0] *= allo; of[n][1] *= allo;
            of[n][2] *= alhi; of[n][3] *= alhi;
        }

        // ---- P -> smem pre-converted to tf32 (CVTs off the PV path) ----
#pragma unroll
        for (int n = 0; n < 2; n++) {
            *(uint2*)&Pu[g * 20 + n * 8 + 2 * t] =
                make_uint2(f2tf(p[n][0]), f2tf(p[n][1]));
            *(uint2*)&Pu[(g + 8) * 20 + n * 8 + 2 * t] =
                make_uint2(f2tf(p[n][2]), f2tf(p[n][3]));
        }
        __syncwarp();

        // ---- PV: 2 k-steps x 8 n-tiles ----
#pragma unroll
        for (int ks = 0; ks < 2; ks++) {
            unsigned pa[4];
            pa[0] = Pu[g * 20 + ks * 8 + t];
            pa[1] = Pu[(g + 8) * 20 + ks * 8 + t];
            pa[2] = Pu[g * 20 + ks * 8 + t + 4];
            pa[3] = Pu[(g + 8) * 20 + ks * 8 + t + 4];
            const unsigned* V0 = Vu + (ks * 8 + t) * VPAD + g;
            const unsigned* V1 = Vu + (ks * 8 + t + 4) * VPAD + g;
#pragma unroll
            for (int n = 0; n < 8; n++)
                mma_tf32(of[n], pa, V0[n * 8], V1[n * 8]);
        }

        // ---- V copy-through (streaming stores) ----
        if (!isnew) {
#pragma unroll
            for (int r = 0; r < 4; r++) {
                const int idx = whalf * 128 + r * 32 + lane;
                const int row = idx >> 4, c4 = idx & 15;
                __stcs((float4*)&presV[(size_t)(tt + row) * HD + c4 * 4],
                       *(const float4*)(Vt + row * VPAD + c4 * 4));
            }
        }
        // (no trailing __syncwarp: next iteration's bar.sync orders the
        //  Ps write-after-read hazard)
    }

    // ---- epilogue: fp16 partial O ----
    const int pbl = (h * NSPLITS + sp) * SQ + qlo;
    const int pbh = (h * NSPLITS + sp) * SQ + qhi;
#pragma unroll
    for (int n = 0; n < 8; n++) {
        *(__half2*)&g_po[(size_t)pbl * HD + n * 8 + 2 * t] =
            __floats2half2_rn(of[n][0], of[n][1]);
        *(__half2*)&g_po[(size_t)pbh * HD + n * 8 + 2 * t] =
            __floats2half2_rn(of[n][2], of[n][3]);
    }
    if (t == 0) {
        g_pml[pbl * 2] = mlo; g_pml[pbl * 2 + 1] = llo;
        g_pml[pbh * 2] = mhi; g_pml[pbh * 2 + 1] = lhi;
    }
}

// ---------------------------------------------------------------------------
// Combine split partials -> g_a. grid (NH, SQ), 512 threads, 8 split-groups,
// 2 accumulator chains per thread; rolled loops (register discipline).
// ---------------------------------------------------------------------------
__global__ __launch_bounds__(512) void combine_kernel()
{
    const int h = blockIdx.x, j = blockIdx.y;
    const int d = threadIdx.x & 63, grp = threadIdx.x >> 6;   // 0..7
    __shared__ float sf[NSPLITS], sl[NSPLITS];
    __shared__ float sO[8][HD], sL[8];

    for (int i = threadIdx.x; i < NSPLITS; i += 512) {
        const float2 ml = *(const float2*)&g_pml[((h * NSPLITS + i) * SQ + j) * 2];
        sf[i] = ml.x;
        sl[i] = ml.y;
    }
    __syncthreads();

    float gm = -1e30f;
    for (int i = 0; i < NSPLITS; i++) gm = fmaxf(gm, sf[i]);
    __syncthreads();
    for (int i = threadIdx.x; i < NSPLITS; i += 512)
        sf[i] = ex2(sf[i] - gm);
    __syncthreads();

    float L0 = 0.f, o0 = 0.f, L1 = 0.f, o1 = 0.f;
    int i = grp;
    for (; i + 8 < NSPLITS; i += 16) {
        const float f0 = sf[i], f1 = sf[i + 8];
        const int x0 = (h * NSPLITS + i) * SQ + j;
        const int x1 = (h * NSPLITS + i + 8) * SQ + j;
        L0 = fmaf(sl[i],     f0, L0);
        o0 = fmaf(f0, __half2float(g_po[(size_t)x0 * HD + d]), o0);
        L1 = fmaf(sl[i + 8], f1, L1);
        o1 = fmaf(f1, __half2float(g_po[(size_t)x1 * HD + d]), o1);
    }
    for (; i < NSPLITS; i += 8) {
        const float f0 = sf[i];
        const int x0 = (h * NSPLITS + i) * SQ + j;
        L0 = fmaf(sl[i], f0, L0);
        o0 = fmaf(f0, __half2float(g_po[(size_t)x0 * HD + d]), o0);
    }
    sO[grp][d] = o0 + o1;
    if (d == 0) sL[grp] = L0 + L1;
    __syncthreads();
    if (grp == 0) {
        float oo = sO[0][d], LL = sL[0];
        for (int u = 1; u < 8; u++) { oo += sO[u][d]; LL += sL[u]; }
        g_a[j * EMB + h * HD + d] = oo / LL;
    }
}

// ---------------------------------------------------------------------------
// Reduce proj partials + bias -> d_out[0 : 32*1024)  (MLP 4)
// ---------------------------------------------------------------------------
__global__ __launch_bounds__(256) void reduce_proj_kernel(
    const float* __restrict__ b, float* __restrict__ dout)
{
    const int c = blockIdx.x * 256 + threadIdx.x;   // 0..1023
    const int r = blockIdx.y;
    float v0 = b[c], v1 = 0.f, v2 = 0.f, v3 = 0.f;
#pragma unroll
    for (int kc = 0; kc < KCH; kc += 4) {
        v0 += g_pprj[((size_t)kc * SQ + r) * EMB + c];
        v1 += g_pprj[((size_t)(kc + 1) * SQ + r) * EMB + c];
        v2 += g_pprj[((size_t)(kc + 2) * SQ + r) * EMB + c];
        v3 += g_pprj[((size_t)(kc + 3) * SQ + r) * EMB + c];
    }
    dout[r * EMB + c] = (v0 + v1) + (v2 + v3);
}

// ---------------------------------------------------------------------------
extern "C" void kernel_launch(void* const* d_in, const int* in_sizes, int n_in,
                              void* d_out, int out_size)
{
    const float* x      = (const float*)d_in[0];
    const float* past   = (const float*)d_in[1];
    const float* w_attn = (const float*)d_in[2];
    const float* b_attn = (const float*)d_in[3];
    const float* w_proj = (const float*)d_in[4];
    const float* b_proj = (const float*)d_in[5];
    float* out = (float*)d_out;

    float* pqkv; cudaGetSymbolAddress((void**)&pqkv, g_pqkv);
    float* pprj; cudaGetSymbolAddress((void**)&pprj, g_pprj);
    float* ga;   cudaGetSymbolAddress((void**)&ga,   g_a);

    cudaFuncSetAttribute(attn_kernel,
                         cudaFuncAttributeMaxDynamicSharedMemorySize, 81920);

    gemm_part_kernel  <<<dim3(24, KCH), 128>>>(x, w_attn, pqkv, 3 * EMB);
    reduce_qkv_kernel <<<dim3(12, SQ),  256>>>(b_attn, out);
    attn_kernel       <<<dim3(NSPLITS, 4), 256, 81920>>>(past, out);
    combine_kernel    <<<dim3(NH, SQ),  512>>>();
    gemm_part_kernel  <<<dim3(8, KCH),  128>>>(ga, w_proj, pprj, EMB);
    reduce_proj_kernel<<<dim3(4, SQ),   256>>>(b_proj, out);
}

// round 15
// speedup vs baseline: 1.0107x; 1.0107x over previous
#include <cuda_runtime.h>
#include <cuda_fp16.h>

#define SQ      32
#define EMB     1024
#define NH      16
#define HD      64
#define PASTN   32768
#define TOT     32800
#define PCHUNK  448
#define NSPLITS 74       // 73 past splits + 1 new-token split
#define KCH     16
#define KCHLEN  64

// Scratch (allocation-free rule: __device__ globals)
__device__ float  g_qkv [SQ * 3 * EMB];
__device__ __half g_po  [NH * NSPLITS * SQ * HD];   // fp16 partial O
__device__ float  g_pml [NH * NSPLITS * SQ * 2];
__device__ float  g_a   [SQ * EMB];
__device__ float  g_pqkv[KCH * SQ * 3 * EMB];
__device__ float  g_pprj[KCH * SQ * EMB];

// ------------------------- helpers ----------------------------------------
__device__ __forceinline__ unsigned long long ffma2(
    unsigned long long a, unsigned long long b, unsigned long long c) {
    unsigned long long d;
    asm("fma.rn.f32x2 %0, %1, %2, %3;" : "=l"(d) : "l"(a), "l"(b), "l"(c));
    return d;
}
__device__ __forceinline__ unsigned long long pack2(float x, float y) {
    unsigned long long r;
    asm("mov.b64 %0, {%1, %2};" : "=l"(r) : "f"(x), "f"(y));
    return r;
}
__device__ __forceinline__ float2 unpack2(unsigned long long v) {
    float2 r;
    asm("mov.b64 {%0, %1}, %2;" : "=f"(r.x), "=f"(r.y) : "l"(v));
    return r;
}
__device__ __forceinline__ float ex2(float x) {
    float r;
    asm("ex2.approx.f32 %0, %1;" : "=f"(r) : "f"(x));
    return r;
}
__device__ __forceinline__ unsigned f2tf(float f) {
    unsigned u;
    asm("cvt.rna.tf32.f32 %0, %1;" : "=r"(u) : "f"(f));
    return u;
}
__device__ __forceinline__ void cp16(unsigned int saddr, const void* gptr) {
    asm volatile("cp.async.cg.shared.global [%0], [%1], 16;"
                 :: "r"(saddr), "l"(gptr));
}
__device__ __forceinline__ void mma_tf32(
    float* d, const unsigned* a, unsigned b0, unsigned b1) {
    asm volatile(
        "mma.sync.aligned.m16n8k8.row.col.f32.tf32.tf32.f32 "
        "{%0,%1,%2,%3}, {%4,%5,%6,%7}, {%8,%9}, {%0,%1,%2,%3};"
        : "+f"(d[0]), "+f"(d[1]), "+f"(d[2]), "+f"(d[3])
        : "r"(a[0]), "r"(a[1]), "r"(a[2]), "r"(a[3]), "r"(b0), "r"(b1));
}

// ---------------------------------------------------------------------------
// Split-K GEMM partial: part[kc][r][C] = x[r][k0:k0+64] @ w[k0:k0+64][C]
// grid (C/128, KCH), block 128.
// ---------------------------------------------------------------------------
__global__ __launch_bounds__(128) void gemm_part_kernel(
    const float* __restrict__ xsrc, const float* __restrict__ w,
    float* __restrict__ part, int C)
{
    __shared__ float xs_t[KCHLEN][36];
    const int c  = blockIdx.x * 128 + threadIdx.x;
    const int k0 = blockIdx.y * KCHLEN;

    {
        const int k = threadIdx.x & 63;
        const int j0 = (threadIdx.x >> 6) * 16;
#pragma unroll
        for (int jj = 0; jj < 16; jj++)
            xs_t[k][j0 + jj] = xsrc[(j0 + jj) * EMB + k0 + k];
    }
    __syncthreads();

    unsigned long long acc[16];
#pragma unroll
    for (int i = 0; i < 16; i++) acc[i] = 0ull;

#pragma unroll 16
    for (int k = 0; k < KCHLEN; k++) {
        const float wv = w[(size_t)(k0 + k) * C + c];
        const unsigned long long w2 = pack2(wv, wv);
#pragma unroll
        for (int r4 = 0; r4 < 8; r4++) {
            const ulonglong2 x4 = *(const ulonglong2*)&xs_t[k][r4 * 4];
            acc[r4 * 2]     = ffma2(x4.x, w2, acc[r4 * 2]);
            acc[r4 * 2 + 1] = ffma2(x4.y, w2, acc[r4 * 2 + 1]);
        }
    }

    float* p = part + (size_t)blockIdx.y * SQ * C + c;
#pragma unroll
    for (int i = 0; i < 16; i++) {
        const float2 v = unpack2(acc[i]);
        p[(size_t)(2 * i)     * C] = v.x;
        p[(size_t)(2 * i + 1) * C] = v.y;
    }
}

// ---------------------------------------------------------------------------
// Reduce qkv partials + bias -> g_qkv ; scatter new K/V rows into present tail
// ---------------------------------------------------------------------------
__global__ __launch_bounds__(256) void reduce_qkv_kernel(
    const float* __restrict__ b, float* __restrict__ dout)
{
    const int c = blockIdx.x * 256 + threadIdx.x;   // 0..3071
    const int r = blockIdx.y;
    float v0 = b[c], v1 = 0.f, v2 = 0.f, v3 = 0.f;
#pragma unroll
    for (int kc = 0; kc < KCH; kc += 4) {
        v0 += g_pqkv[((size_t)kc * SQ + r) * (3 * EMB) + c];
        v1 += g_pqkv[((size_t)(kc + 1) * SQ + r) * (3 * EMB) + c];
        v2 += g_pqkv[((size_t)(kc + 2) * SQ + r) * (3 * EMB) + c];
        v3 += g_pqkv[((size_t)(kc + 3) * SQ + r) * (3 * EMB) + c];
    }
    const float v = (v0 + v1) + (v2 + v3);
    g_qkv[r * 3 * EMB + c] = v;
    if (c >= EMB) {
        const int which = (c >= 2 * EMB) ? 1 : 0;   // 0=K, 1=V
        const int cc = c - EMB - which * EMB;
        const int h = cc / HD, d = cc % HD;
        dout[(size_t)SQ * EMB
             + ((size_t)which * NH + h) * (size_t)TOT * HD
             + (size_t)(PASTN + r) * HD + d] = v;
    }
}

// ---------------------------------------------------------------------------
// Attention via mma.sync tf32. CTA = 256 thr = 8 warps = 4 heads x 2 q-halves.
// grid (NSPLITS, 4) = 296 CTAs. Per-pair named barriers.
// SAFE pipeline: wait_group 0 -> pair-bar -> prefetch(i+1) -> compute.
// (Cross-warp smem reads are only valid because BOTH warps' waits precede
//  the shared barrier — do not reorder.)
// smem: K[4][2][16][68] + V[4][2][16][72] + Ps[8][16][20] = 80 KB.
// ---------------------------------------------------------------------------
#define KPAD 68
#define VPAD 72
#define K_OFF(head, buf) ((head) * 2176 + (buf) * 1088)
#define V_OFF(head, buf) (8704 + (head) * 2304 + (buf) * 1152)
#define P_OFF(warpid)    (17920 + (warpid) * 320)

__global__ __launch_bounds__(256) void attn_kernel(
    const float* __restrict__ past, float* __restrict__ dout)
{
    extern __shared__ float smem[];
    const int warp = threadIdx.x >> 5, lane = threadIdx.x & 31;
    const int head = warp >> 1, whalf = warp & 1;
    const int g = lane >> 2, t = lane & 3;
    const int sp = blockIdx.x;
    const int h  = blockIdx.y * 4 + head;

    const bool isnew = (sp == NSPLITS - 1);
    int t0, tend;
    if (isnew)                  { t0 = PASTN;       tend = TOT; }
    else if (sp == NSPLITS - 2) { t0 = sp * PCHUNK; tend = PASTN; }
    else                        { t0 = sp * PCHUNK; tend = t0 + PCHUNK; }
    const int nt = (tend - t0) >> 4;

    // ---- Q fragments: 8 k-steps x 4 regs (rows qlo=whalf*16+g, qhi=+8) ----
    const int qlo = whalf * 16 + g, qhi = qlo + 8;
    const float qc = 0.125f * 1.4426950408889634f;   // 1/sqrt(d) * log2(e)
    unsigned qf[32];
    {
        const float* qL = g_qkv + qlo * 3 * EMB + h * HD;
        const float* qH = g_qkv + qhi * 3 * EMB + h * HD;
#pragma unroll
        for (int ks = 0; ks < 8; ks++) {
            qf[ks * 4 + 0] = f2tf(qL[ks * 8 + t]     * qc);
            qf[ks * 4 + 1] = f2tf(qH[ks * 8 + t]     * qc);
            qf[ks * 4 + 2] = f2tf(qL[ks * 8 + t + 4] * qc);
            qf[ks * 4 + 3] = f2tf(qH[ks * 8 + t + 4] * qc);
        }
    }

    float of[8][4];
#pragma unroll
    for (int n = 0; n < 8; n++)
#pragma unroll
        for (int r = 0; r < 4; r++) of[n][r] = 0.f;
    float mlo = -1e30f, mhi = -1e30f, llo = 0.f, lhi = 0.f;

    float* presK = dout + SQ * EMB + (size_t)h * TOT * HD;
    float* presV = presK + (size_t)NH * TOT * HD;
    const float* srcK = isnew ? (presK + (size_t)t0 * HD)
                              : (past + ((size_t)h * PASTN + t0) * (size_t)HD);
    const float* srcV = isnew ? (presV + (size_t)t0 * HD)
                              : (past + ((size_t)(NH + h) * PASTN + t0) * (size_t)HD);

    float* Ps = smem + P_OFF(warp);
    unsigned* Pu = (unsigned*)Ps;
    const unsigned KsA = (unsigned)__cvta_generic_to_shared(smem);

    // ---- prefetch tile 0 (this warp loads its half of the head's rows) ----
#pragma unroll
    for (int r = 0; r < 4; r++) {
        const int idx = whalf * 128 + r * 32 + lane;   // 0..255 over pair
        const int row = idx >> 4, c4 = idx & 15;
        cp16(KsA + (unsigned)(K_OFF(head, 0) + row * KPAD + c4 * 4) * 4u,
             srcK + row * HD + c4 * 4);
        cp16(KsA + (unsigned)(V_OFF(head, 0) + row * VPAD + c4 * 4) * 4u,
             srcV + row * HD + c4 * 4);
    }
    asm volatile("cp.async.commit_group;");

    for (int i = 0; i < nt; i++) {
        const int buf = i & 1;
        // Tile i (K and V, this warp's halves) landed.
        asm volatile("cp.async.wait_group 0;");
        // Pair barrier: partner's halves also landed (its wait precedes its
        // barrier arrival), and partner finished compute i-1 -> the buffer
        // we prefetch into below is free.
        asm volatile("bar.sync %0, 64;" :: "r"(head + 1));

        if (i + 1 < nt) {
            const size_t gb = (size_t)(i + 1) * 16 * HD;
            const int bo = buf ^ 1;
#pragma unroll
            for (int r = 0; r < 4; r++) {
                const int idx = whalf * 128 + r * 32 + lane;
                const int row = idx >> 4, c4 = idx & 15;
                cp16(KsA + (unsigned)(K_OFF(head, bo) + row * KPAD + c4 * 4) * 4u,
                     srcK + gb + row * HD + c4 * 4);
                cp16(KsA + (unsigned)(V_OFF(head, bo) + row * VPAD + c4 * 4) * 4u,
                     srcV + gb + row * HD + c4 * 4);
            }
            asm volatile("cp.async.commit_group;");
        }

        const float* Kt = smem + K_OFF(head, buf);
        const float* Vt = smem + V_OFF(head, buf);
        const unsigned* Ku = (const unsigned*)Kt;
        const unsigned* Vu = (const unsigned*)Vt;
        const int tt = t0 + i * 16;

        // ---- QK: 2 n-tiles x 8 k-steps (2 acc chains each) ----
        float s[2][4];
#pragma unroll
        for (int n = 0; n < 2; n++) {
            float ca[4] = {0.f, 0.f, 0.f, 0.f};
            float cb[4] = {0.f, 0.f, 0.f, 0.f};
            const unsigned* Kr = Ku + (n * 8 + g) * KPAD + t;
#pragma unroll
            for (int ks = 0; ks < 4; ks++) {
                mma_tf32(ca, qf + 4 * ks,       Kr[ks * 8],       Kr[ks * 8 + 4]);
                mma_tf32(cb, qf + 4 * (ks + 4), Kr[(ks + 4) * 8], Kr[(ks + 4) * 8 + 4]);
            }
#pragma unroll
            for (int r = 0; r < 4; r++) s[n][r] = ca[r] + cb[r];
        }

        // ---- K copy-through (streaming stores; data landed pre-barrier) ----
        if (!isnew) {
#pragma unroll
            for (int r = 0; r < 4; r++) {
                const int idx = whalf * 128 + r * 32 + lane;
                const int row = idx >> 4, c4 = idx & 15;
                __stcs((float4*)&presK[(size_t)(tt + row) * HD + c4 * 4],
                       *(const float4*)(Kt + row * KPAD + c4 * 4));
            }
        }

        // ---- causal mask (new-token split only) ----
        if (isnew) {
            const int kb = i * 16;
#pragma unroll
            for (int n = 0; n < 2; n++) {
                const int col = n * 8 + 2 * t;
                if (kb + col     > qlo) s[n][0] = -1e30f;
                if (kb + col + 1 > qlo) s[n][1] = -1e30f;
                if (kb + col     > qhi) s[n][2] = -1e30f;
                if (kb + col + 1 > qhi) s[n][3] = -1e30f;
            }
        }

        // ---- online softmax (quad shfl reductions) ----
        float vlo = fmaxf(fmaxf(s[0][0], s[0][1]), fmaxf(s[1][0], s[1][1]));
        float vhi = fmaxf(fmaxf(s[0][2], s[0][3]), fmaxf(s[1][2], s[1][3]));
        vlo = fmaxf(vlo, __shfl_xor_sync(0xffffffffu, vlo, 1));
        vlo = fmaxf(vlo, __shfl_xor_sync(0xffffffffu, vlo, 2));
        vhi = fmaxf(vhi, __shfl_xor_sync(0xffffffffu, vhi, 1));
        vhi = fmaxf(vhi, __shfl_xor_sync(0xffffffffu, vhi, 2));
        const float nmlo = fmaxf(mlo, vlo), nmhi = fmaxf(mhi, vhi);
        const float allo = ex2(mlo - nmlo), alhi = ex2(mhi - nmhi);
        mlo = nmlo; mhi = nmhi;

        float p[2][4];
#pragma unroll
        for (int n = 0; n < 2; n++) {
            p[n][0] = ex2(s[n][0] - nmlo);
            p[n][1] = ex2(s[n][1] - nmlo);
            p[n][2] = ex2(s[n][2] - nmhi);
            p[n][3] = ex2(s[n][3] - nmhi);
        }
        float slo = (p[0][0] + p[0][1]) + (p[1][0] + p[1][1]);
        float shi = (p[0][2] + p[0][3]) + (p[1][2] + p[1][3]);
        slo += __shfl_xor_sync(0xffffffffu, slo, 1);
        slo += __shfl_xor_sync(0xffffffffu, slo, 2);
        shi += __shfl_xor_sync(0xffffffffu, shi, 1);
        shi += __shfl_xor_sync(0xffffffffu, shi, 2);
        llo = llo * allo + slo;
        lhi = lhi * alhi + shi;

#pragma unroll
        for (int n = 0; n < 8; n++) {
            of[n][0] *= allo; of[n][1] *= allo;
            of[n][2] *= alhi; of[n][3] *= alhi;
        }

        // ---- P -> smem pre-converted to tf32 (CVTs off the PV path) ----
#pragma unroll
        for (int n = 0; n < 2; n++) {
            *(uint2*)&Pu[g * 20 + n * 8 + 2 * t] =
                make_uint2(f2tf(p[n][0]), f2tf(p[n][1]));
            *(uint2*)&Pu[(g + 8) * 20 + n * 8 + 2 * t] =
                make_uint2(f2tf(p[n][2]), f2tf(p[n][3]));
        }
        __syncwarp();

        // ---- PV: 2 k-steps x 8 n-tiles ----
#pragma unroll
        for (int ks = 0; ks < 2; ks++) {
            unsigned pa[4];
            pa[0] = Pu[g * 20 + ks * 8 + t];
            pa[1] = Pu[(g + 8) * 20 + ks * 8 + t];
            pa[2] = Pu[g * 20 + ks * 8 + t + 4];
            pa[3] = Pu[(g + 8) * 20 + ks * 8 + t + 4];
            const unsigned* V0 = Vu + (ks * 8 + t) * VPAD + g;
            const unsigned* V1 = Vu + (ks * 8 + t + 4) * VPAD + g;
#pragma unroll
            for (int n = 0; n < 8; n++)
                mma_tf32(of[n], pa, V0[n * 8], V1[n * 8]);
        }

        // ---- V copy-through (streaming stores) ----
        if (!isnew) {
#pragma unroll
            for (int r = 0; r < 4; r++) {
                const int idx = whalf * 128 + r * 32 + lane;
                const int row = idx >> 4, c4 = idx & 15;
                __stcs((float4*)&presV[(size_t)(tt + row) * HD + c4 * 4],
                       *(const float4*)(Vt + row * VPAD + c4 * 4));
            }
        }
        // (no trailing __syncwarp: next iteration's bar.sync orders the
        //  Ps write-after-read hazard)
    }

    // ---- epilogue: fp16 partial O ----
    const int pbl = (h * NSPLITS + sp) * SQ + qlo;
    const int pbh = (h * NSPLITS + sp) * SQ + qhi;
#pragma unroll
    for (int n = 0; n < 8; n++) {
        *(__half2*)&g_po[(size_t)pbl * HD + n * 8 + 2 * t] =
            __floats2half2_rn(of[n][0], of[n][1]);
        *(__half2*)&g_po[(size_t)pbh * HD + n * 8 + 2 * t] =
            __floats2half2_rn(of[n][2], of[n][3]);
    }
    if (t == 0) {
        g_pml[pbl * 2] = mlo; g_pml[pbl * 2 + 1] = llo;
        g_pml[pbh * 2] = mhi; g_pml[pbh * 2 + 1] = lhi;
    }
}

// ---------------------------------------------------------------------------
// Combine split partials -> g_a. grid (NH, SQ), 512 threads:
// 16 split-groups x 32 dim-pairs; one 4-byte half2 LDG per (split, thread).
// ---------------------------------------------------------------------------
__global__ __launch_bounds__(512) void combine_kernel()
{
    const int h = blockIdx.x, j = blockIdx.y;
    const int d2  = threadIdx.x & 31;        // dim pair: dims 2*d2, 2*d2+1
    const int grp = threadIdx.x >> 5;        // 0..15
    __shared__ float  sf[NSPLITS], sl[NSPLITS];
    __shared__ float2 sO[16][32];
    __shared__ float  sL[16];

    for (int i = threadIdx.x; i < NSPLITS; i += 512) {
        const float2 ml = *(const float2*)&g_pml[((h * NSPLITS + i) * SQ + j) * 2];
        sf[i] = ml.x;
        sl[i] = ml.y;
    }
    __syncthreads();

    float gm = -1e30f;
    for (int i = 0; i < NSPLITS; i++) gm = fmaxf(gm, sf[i]);
    __syncthreads();
    for (int i = threadIdx.x; i < NSPLITS; i += 512)
        sf[i] = ex2(sf[i] - gm);
    __syncthreads();

    float L = 0.f, ox = 0.f, oy = 0.f;
    for (int i = grp; i < NSPLITS; i += 16) {
        const float f = sf[i];
        const int x = (h * NSPLITS + i) * SQ + j;
        L = fmaf(sl[i], f, L);
        const float2 v = __half22float2(
            *(const __half2*)&g_po[(size_t)x * HD + 2 * d2]);
        ox = fmaf(f, v.x, ox);
        oy = fmaf(f, v.y, oy);
    }
    sO[grp][d2] = make_float2(ox, oy);
    if (d2 == 0) sL[grp] = L;
    __syncthreads();
    if (grp == 0) {
        float2 oo = sO[0][d2];
        float LL = sL[0];
        for (int u = 1; u < 16; u++) {
            oo.x += sO[u][d2].x;
            oo.y += sO[u][d2].y;
            LL += sL[u];
        }
        const float inv = 1.f / LL;
        *(float2*)&g_a[j * EMB + h * HD + 2 * d2] =
            make_float2(oo.x * inv, oo.y * inv);
    }
}

// ---------------------------------------------------------------------------
// Reduce proj partials + bias -> d_out[0 : 32*1024)  (MLP 4)
// ---------------------------------------------------------------------------
__global__ __launch_bounds__(256) void reduce_proj_kernel(
    const float* __restrict__ b, float* __restrict__ dout)
{
    const int c = blockIdx.x * 256 + threadIdx.x;   // 0..1023
    const int r = blockIdx.y;
    float v0 = b[c], v1 = 0.f, v2 = 0.f, v3 = 0.f;
#pragma unroll
    for (int kc = 0; kc < KCH; kc += 4) {
        v0 += g_pprj[((size_t)kc * SQ + r) * EMB + c];
        v1 += g_pprj[((size_t)(kc + 1) * SQ + r) * EMB + c];
        v2 += g_pprj[((size_t)(kc + 2) * SQ + r) * EMB + c];
        v3 += g_pprj[((size_t)(kc + 3) * SQ + r) * EMB + c];
    }
    dout[r * EMB + c] = (v0 + v1) + (v2 + v3);
}

// ---------------------------------------------------------------------------
extern "C" void kernel_launch(void* const* d_in, const int* in_sizes, int n_in,
                              void* d_out, int out_size)
{
    const float* x      = (const float*)d_in[0];
    const float* past   = (const float*)d_in[1];
    const float* w_attn = (const float*)d_in[2];
    const float* b_attn = (const float*)d_in[3];
    const float* w_proj = (const float*)d_in[4];
    const float* b_proj = (const float*)d_in[5];
    float* out = (float*)d_out;

    float* pqkv; cudaGetSymbolAddress((void**)&pqkv, g_pqkv);
    float* pprj; cudaGetSymbolAddress((void**)&pprj, g_pprj);
    float* ga;   cudaGetSymbolAddress((void**)&ga,   g_a);

    cudaFuncSetAttribute(attn_kernel,
                         cudaFuncAttributeMaxDynamicSharedMemorySize, 81920);

    gemm_part_kernel  <<<dim3(24, KCH), 128>>>(x, w_attn, pqkv, 3 * EMB);
    reduce_qkv_kernel <<<dim3(12, SQ),  256>>>(b_attn, out);
    attn_kernel       <<<dim3(NSPLITS, 4), 256, 81920>>>(past, out);
    combine_kernel    <<<dim3(NH, SQ),  512>>>();
    gemm_part_kernel  <<<dim3(8, KCH),  128>>>(ga, w_proj, pprj, EMB);
    reduce_proj_kernel<<<dim3(4, SQ),   256>>>(b_proj, out);
}

// round 16
// speedup vs baseline: 1.0305x; 1.0196x over previous
#include <cuda_runtime.h>
#include <cuda_fp16.h>

#define SQ      32
#define EMB     1024
#define NH      16
#define HD      64
#define PASTN   32768
#define TOT     32800
#define NSPLITS 74       // 73 past splits (28/29 tiles, balanced) + 1 new-token split
#define KCH     16
#define KCHLEN  64

// Scratch (allocation-free rule: __device__ globals)
__device__ float  g_qkv [SQ * 3 * EMB];
__device__ __half g_po  [NH * NSPLITS * SQ * HD];   // fp16 partial O
__device__ float  g_pml [NH * NSPLITS * SQ * 2];
__device__ float  g_a   [SQ * EMB];
__device__ float  g_pqkv[KCH * SQ * 3 * EMB];
__device__ float  g_pprj[KCH * SQ * EMB];

// ------------------------- helpers ----------------------------------------
__device__ __forceinline__ unsigned long long ffma2(
    unsigned long long a, unsigned long long b, unsigned long long c) {
    unsigned long long d;
    asm("fma.rn.f32x2 %0, %1, %2, %3;" : "=l"(d) : "l"(a), "l"(b), "l"(c));
    return d;
}
__device__ __forceinline__ unsigned long long pack2(float x, float y) {
    unsigned long long r;
    asm("mov.b64 %0, {%1, %2};" : "=l"(r) : "f"(x), "f"(y));
    return r;
}
__device__ __forceinline__ float2 unpack2(unsigned long long v) {
    float2 r;
    asm("mov.b64 {%0, %1}, %2;" : "=f"(r.x), "=f"(r.y) : "l"(v));
    return r;
}
__device__ __forceinline__ float ex2(float x) {
    float r;
    asm("ex2.approx.f32 %0, %1;" : "=f"(r) : "f"(x));
    return r;
}
__device__ __forceinline__ unsigned f2tf(float f) {
    unsigned u;
    asm("cvt.rna.tf32.f32 %0, %1;" : "=r"(u) : "f"(f));
    return u;
}
__device__ __forceinline__ void cp16(unsigned int saddr, const void* gptr) {
    asm volatile("cp.async.cg.shared.global [%0], [%1], 16;"
                 :: "r"(saddr), "l"(gptr));
}
__device__ __forceinline__ void mma_tf32(
    float* d, const unsigned* a, unsigned b0, unsigned b1) {
    asm volatile(
        "mma.sync.aligned.m16n8k8.row.col.f32.tf32.tf32.f32 "
        "{%0,%1,%2,%3}, {%4,%5,%6,%7}, {%8,%9}, {%0,%1,%2,%3};"
        : "+f"(d[0]), "+f"(d[1]), "+f"(d[2]), "+f"(d[3])
        : "r"(a[0]), "r"(a[1]), "r"(a[2]), "r"(a[3]), "r"(b0), "r"(b1));
}

// ---------------------------------------------------------------------------
// Split-K GEMM partial: part[kc][r][C] = x[r][k0:k0+64] @ w[k0:k0+64][C]
// grid (C/128, KCH), block 128.
// ---------------------------------------------------------------------------
__global__ __launch_bounds__(128) void gemm_part_kernel(
    const float* __restrict__ xsrc, const float* __restrict__ w,
    float* __restrict__ part, int C)
{
    __shared__ float xs_t[KCHLEN][36];
    const int c  = blockIdx.x * 128 + threadIdx.x;
    const int k0 = blockIdx.y * KCHLEN;

    {
        const int k = threadIdx.x & 63;
        const int j0 = (threadIdx.x >> 6) * 16;
#pragma unroll
        for (int jj = 0; jj < 16; jj++)
            xs_t[k][j0 + jj] = xsrc[(j0 + jj) * EMB + k0 + k];
    }
    __syncthreads();

    unsigned long long acc[16];
#pragma unroll
    for (int i = 0; i < 16; i++) acc[i] = 0ull;

#pragma unroll 16
    for (int k = 0; k < KCHLEN; k++) {
        const float wv = w[(size_t)(k0 + k) * C + c];
        const unsigned long long w2 = pack2(wv, wv);
#pragma unroll
        for (int r4 = 0; r4 < 8; r4++) {
            const ulonglong2 x4 = *(const ulonglong2*)&xs_t[k][r4 * 4];
            acc[r4 * 2]     = ffma2(x4.x, w2, acc[r4 * 2]);
            acc[r4 * 2 + 1] = ffma2(x4.y, w2, acc[r4 * 2 + 1]);
        }
    }

    float* p = part + (size_t)blockIdx.y * SQ * C + c;
#pragma unroll
    for (int i = 0; i < 16; i++) {
        const float2 v = unpack2(acc[i]);
        p[(size_t)(2 * i)     * C] = v.x;
        p[(size_t)(2 * i + 1) * C] = v.y;
    }
}

// ---------------------------------------------------------------------------
// Reduce qkv partials + bias -> g_qkv ; scatter new K/V rows into present tail
// ---------------------------------------------------------------------------
__global__ __launch_bounds__(256) void reduce_qkv_kernel(
    const float* __restrict__ b, float* __restrict__ dout)
{
    const int c = blockIdx.x * 256 + threadIdx.x;   // 0..3071
    const int r = blockIdx.y;
    float v0 = b[c], v1 = 0.f, v2 = 0.f, v3 = 0.f;
#pragma unroll
    for (int kc = 0; kc < KCH; kc += 4) {
        v0 += g_pqkv[((size_t)kc * SQ + r) * (3 * EMB) + c];
        v1 += g_pqkv[((size_t)(kc + 1) * SQ + r) * (3 * EMB) + c];
        v2 += g_pqkv[((size_t)(kc + 2) * SQ + r) * (3 * EMB) + c];
        v3 += g_pqkv[((size_t)(kc + 3) * SQ + r) * (3 * EMB) + c];
    }
    const float v = (v0 + v1) + (v2 + v3);
    g_qkv[r * 3 * EMB + c] = v;
    if (c >= EMB) {
        const int which = (c >= 2 * EMB) ? 1 : 0;   // 0=K, 1=V
        const int cc = c - EMB - which * EMB;
        const int h = cc / HD, d = cc % HD;
        dout[(size_t)SQ * EMB
             + ((size_t)which * NH + h) * (size_t)TOT * HD
             + (size_t)(PASTN + r) * HD + d] = v;
    }
}

// ---------------------------------------------------------------------------
// Attention via mma.sync tf32. CTA = 256 thr = 8 warps = 4 heads x 2 q-halves.
// grid (NSPLITS, 4) = 296 CTAs = 1 wave. Balanced splits: 69x28 + 4x29 tiles.
// Per-pair named barriers. SAFE pipeline:
//   wait_group 0 -> pair-bar -> prefetch(i+1) -> compute.
// smem: K[4][2][16][68] + V[4][2][16][72] + Ps[8][16][20] = 80 KB.
// ---------------------------------------------------------------------------
#define KPAD 68
#define VPAD 72
#define K_OFF(head, buf) ((head) * 2176 + (buf) * 1088)
#define V_OFF(head, buf) (8704 + (head) * 2304 + (buf) * 1152)
#define P_OFF(warpid)    (17920 + (warpid) * 320)

__global__ __launch_bounds__(256) void attn_kernel(
    const float* __restrict__ past, float* __restrict__ dout)
{
    extern __shared__ float smem[];
    const int warp = threadIdx.x >> 5, lane = threadIdx.x & 31;
    const int head = warp >> 1, whalf = warp & 1;
    const int g = lane >> 2, t = lane & 3;
    const int sp = blockIdx.x;
    const int h  = blockIdx.y * 4 + head;

    const bool isnew = (sp == NSPLITS - 1);
    int t0, nt;
    if (isnew) { t0 = PASTN; nt = (TOT - PASTN) >> 4; }
    else {       // balanced tiling: 2048 tiles over 73 splits = 69x28 + 4x29
        const int st = sp * 28 + min(sp, 4);
        t0 = st << 4;
        nt = 28 + (sp < 4 ? 1 : 0);
    }

    // ---- Q fragments: 8 k-steps x 4 regs (rows qlo=whalf*16+g, qhi=+8) ----
    const int qlo = whalf * 16 + g, qhi = qlo + 8;
    const float qc = 0.125f * 1.4426950408889634f;   // 1/sqrt(d) * log2(e)
    unsigned qf[32];
    {
        const float* qL = g_qkv + qlo * 3 * EMB + h * HD;
        const float* qH = g_qkv + qhi * 3 * EMB + h * HD;
#pragma unroll
        for (int ks = 0; ks < 8; ks++) {
            qf[ks * 4 + 0] = f2tf(qL[ks * 8 + t]     * qc);
            qf[ks * 4 + 1] = f2tf(qH[ks * 8 + t]     * qc);
            qf[ks * 4 + 2] = f2tf(qL[ks * 8 + t + 4] * qc);
            qf[ks * 4 + 3] = f2tf(qH[ks * 8 + t + 4] * qc);
        }
    }

    float of[8][4];
#pragma unroll
    for (int n = 0; n < 8; n++)
#pragma unroll
        for (int r = 0; r < 4; r++) of[n][r] = 0.f;
    float mlo = -1e30f, mhi = -1e30f, llo = 0.f, lhi = 0.f;

    float* presK = dout + SQ * EMB + (size_t)h * TOT * HD;
    float* presV = presK + (size_t)NH * TOT * HD;
    const float* srcK = isnew ? (presK + (size_t)t0 * HD)
                              : (past + ((size_t)h * PASTN + t0) * (size_t)HD);
    const float* srcV = isnew ? (presV + (size_t)t0 * HD)
                              : (past + ((size_t)(NH + h) * PASTN + t0) * (size_t)HD);

    float* Ps = smem + P_OFF(warp);
    unsigned* Pu = (unsigned*)Ps;
    const unsigned KsA = (unsigned)__cvta_generic_to_shared(smem);

    // ---- prefetch tile 0 (this warp loads its half of the head's rows) ----
#pragma unroll
    for (int r = 0; r < 4; r++) {
        const int idx = whalf * 128 + r * 32 + lane;   // 0..255 over pair
        const int row = idx >> 4, c4 = idx & 15;
        cp16(KsA + (unsigned)(K_OFF(head, 0) + row * KPAD + c4 * 4) * 4u,
             srcK + row * HD + c4 * 4);
        cp16(KsA + (unsigned)(V_OFF(head, 0) + row * VPAD + c4 * 4) * 4u,
             srcV + row * HD + c4 * 4);
    }
    asm volatile("cp.async.commit_group;");

    for (int i = 0; i < nt; i++) {
        const int buf = i & 1;
        // Tile i (K and V, this warp's halves) landed.
        asm volatile("cp.async.wait_group 0;");
        // Pair barrier: partner's halves also landed (its wait precedes its
        // barrier arrival), and partner finished compute i-1 -> the buffer
        // we prefetch into below is free.
        asm volatile("bar.sync %0, 64;" :: "r"(head + 1));

        if (i + 1 < nt) {
            const size_t gb = (size_t)(i + 1) * 16 * HD;
            const int bo = buf ^ 1;
#pragma unroll
            for (int r = 0; r < 4; r++) {
                const int idx = whalf * 128 + r * 32 + lane;
                const int row = idx >> 4, c4 = idx & 15;
                cp16(KsA + (unsigned)(K_OFF(head, bo) + row * KPAD + c4 * 4) * 4u,
                     srcK + gb + row * HD + c4 * 4);
                cp16(KsA + (unsigned)(V_OFF(head, bo) + row * VPAD + c4 * 4) * 4u,
                     srcV + gb + row * HD + c4 * 4);
            }
            asm volatile("cp.async.commit_group;");
        }

        const float* Kt = smem + K_OFF(head, buf);
        const float* Vt = smem + V_OFF(head, buf);
        const unsigned* Ku = (const unsigned*)Kt;
        const unsigned* Vu = (const unsigned*)Vt;
        const int tt = t0 + i * 16;

        // ---- QK: 2 n-tiles x 8 k-steps (2 acc chains each) ----
        float s[2][4];
#pragma unroll
        for (int n = 0; n < 2; n++) {
            float ca[4] = {0.f, 0.f, 0.f, 0.f};
            float cb[4] = {0.f, 0.f, 0.f, 0.f};
            const unsigned* Kr = Ku + (n * 8 + g) * KPAD + t;
#pragma unroll
            for (int ks = 0; ks < 4; ks++) {
                mma_tf32(ca, qf + 4 * ks,       Kr[ks * 8],       Kr[ks * 8 + 4]);
                mma_tf32(cb, qf + 4 * (ks + 4), Kr[(ks + 4) * 8], Kr[(ks + 4) * 8 + 4]);
            }
#pragma unroll
            for (int r = 0; r < 4; r++) s[n][r] = ca[r] + cb[r];
        }

        // ---- K copy-through (streaming stores; data landed pre-barrier) ----
        if (!isnew) {
#pragma unroll
            for (int r = 0; r < 4; r++) {
                const int idx = whalf * 128 + r * 32 + lane;
                const int row = idx >> 4, c4 = idx & 15;
                __stcs((float4*)&presK[(size_t)(tt + row) * HD + c4 * 4],
                       *(const float4*)(Kt + row * KPAD + c4 * 4));
            }
        }

        // ---- causal mask (new-token split only) ----
        if (isnew) {
            const int kb = i * 16;
#pragma unroll
            for (int n = 0; n < 2; n++) {
                const int col = n * 8 + 2 * t;
                if (kb + col     > qlo) s[n][0] = -1e30f;
                if (kb + col + 1 > qlo) s[n][1] = -1e30f;
                if (kb + col     > qhi) s[n][2] = -1e30f;
                if (kb + col + 1 > qhi) s[n][3] = -1e30f;
            }
        }

        // ---- online softmax (quad shfl reductions) ----
        float vlo = fmaxf(fmaxf(s[0][0], s[0][1]), fmaxf(s[1][0], s[1][1]));
        float vhi = fmaxf(fmaxf(s[0][2], s[0][3]), fmaxf(s[1][2], s[1][3]));
        vlo = fmaxf(vlo, __shfl_xor_sync(0xffffffffu, vlo, 1));
        vlo = fmaxf(vlo, __shfl_xor_sync(0xffffffffu, vlo, 2));
        vhi = fmaxf(vhi, __shfl_xor_sync(0xffffffffu, vhi, 1));
        vhi = fmaxf(vhi, __shfl_xor_sync(0xffffffffu, vhi, 2));
        const float nmlo = fmaxf(mlo, vlo), nmhi = fmaxf(mhi, vhi);
        const float allo = ex2(mlo - nmlo), alhi = ex2(mhi - nmhi);
        mlo = nmlo; mhi = nmhi;

        float p[2][4];
#pragma unroll
        for (int n = 0; n < 2; n++) {
            p[n][0] = ex2(s[n][0] - nmlo);
            p[n][1] = ex2(s[n][1] - nmlo);
            p[n][2] = ex2(s[n][2] - nmhi);
            p[n][3] = ex2(s[n][3] - nmhi);
        }
        float slo = (p[0][0] + p[0][1]) + (p[1][0] + p[1][1]);
        float shi = (p[0][2] + p[0][3]) + (p[1][2] + p[1][3]);
        slo += __shfl_xor_sync(0xffffffffu, slo, 1);
        slo += __shfl_xor_sync(0xffffffffu, slo, 2);
        shi += __shfl_xor_sync(0xffffffffu, shi, 1);
        shi += __shfl_xor_sync(0xffffffffu, shi, 2);
        llo = llo * allo + slo;
        lhi = lhi * alhi + shi;

#pragma unroll
        for (int n = 0; n < 8; n++) {
            of[n][0] *= allo; of[n][1] *= allo;
            of[n][2] *= alhi; of[n][3] *= alhi;
        }

        // ---- P -> smem pre-converted to tf32 (CVTs off the PV path) ----
#pragma unroll
        for (int n = 0; n < 2; n++) {
            *(uint2*)&Pu[g * 20 + n * 8 + 2 * t] =
                make_uint2(f2tf(p[n][0]), f2tf(p[n][1]));
            *(uint2*)&Pu[(g + 8) * 20 + n * 8 + 2 * t] =
                make_uint2(f2tf(p[n][2]), f2tf(p[n][3]));
        }
        __syncwarp();

        // ---- PV: 2 k-steps x 8 n-tiles ----
#pragma unroll
        for (int ks = 0; ks < 2; ks++) {
            unsigned pa[4];
            pa[0] = Pu[g * 20 + ks * 8 + t];
            pa[1] = Pu[(g + 8) * 20 + ks * 8 + t];
            pa[2] = Pu[g * 20 + ks * 8 + t + 4];
            pa[3] = Pu[(g + 8) * 20 + ks * 8 + t + 4];
            const unsigned* V0 = Vu + (ks * 8 + t) * VPAD + g;
            const unsigned* V1 = Vu + (ks * 8 + t + 4) * VPAD + g;
#pragma unroll
            for (int n = 0; n < 8; n++)
                mma_tf32(of[n], pa, V0[n * 8], V1[n * 8]);
        }

        // ---- V copy-through (streaming stores) ----
        if (!isnew) {
#pragma unroll
            for (int r = 0; r < 4; r++) {
                const int idx = whalf * 128 + r * 32 + lane;
                const int row = idx >> 4, c4 = idx & 15;
                __stcs((float4*)&presV[(size_t)(tt + row) * HD + c4 * 4],
                       *(const float4*)(Vt + row * VPAD + c4 * 4));
            }
        }
        // (no trailing __syncwarp: next iteration's bar.sync orders the
        //  Ps write-after-read hazard)
    }

    // ---- epilogue: fp16 partial O ----
    const int pbl = (h * NSPLITS + sp) * SQ + qlo;
    const int pbh = (h * NSPLITS + sp) * SQ + qhi;
#pragma unroll
    for (int n = 0; n < 8; n++) {
        *(__half2*)&g_po[(size_t)pbl * HD + n * 8 + 2 * t] =
            __floats2half2_rn(of[n][0], of[n][1]);
        *(__half2*)&g_po[(size_t)pbh * HD + n * 8 + 2 * t] =
            __floats2half2_rn(of[n][2], of[n][3]);
    }
    if (t == 0) {
        g_pml[pbl * 2] = mlo; g_pml[pbl * 2 + 1] = llo;
        g_pml[pbh * 2] = mhi; g_pml[pbh * 2 + 1] = lhi;
    }
}

// ---------------------------------------------------------------------------
// Combine split partials -> g_a. grid (NH, SQ), 512 threads:
// 16 split-groups x 32 dim-pairs; half2 loads, two explicit load chains.
// ---------------------------------------------------------------------------
__global__ __launch_bounds__(512) void combine_kernel()
{
    const int h = blockIdx.x, j = blockIdx.y;
    const int d2  = threadIdx.x & 31;        // dim pair: dims 2*d2, 2*d2+1
    const int grp = threadIdx.x >> 5;        // 0..15
    __shared__ float  sf[NSPLITS], sl[NSPLITS];
    __shared__ float2 sO[16][32];
    __shared__ float  sL[16];

    for (int i = threadIdx.x; i < NSPLITS; i += 512) {
        const float2 ml = *(const float2*)&g_pml[((h * NSPLITS + i) * SQ + j) * 2];
        sf[i] = ml.x;
        sl[i] = ml.y;
    }
    __syncthreads();

    float gm = -1e30f;
    for (int i = 0; i < NSPLITS; i++) gm = fmaxf(gm, sf[i]);
    __syncthreads();
    for (int i = threadIdx.x; i < NSPLITS; i += 512)
        sf[i] = ex2(sf[i] - gm);
    __syncthreads();

    float L0 = 0.f, ox0 = 0.f, oy0 = 0.f;
    float L1 = 0.f, ox1 = 0.f, oy1 = 0.f;
    int i = grp;
    for (; i + 16 < NSPLITS; i += 32) {
        const float f0 = sf[i], f1 = sf[i + 16];
        const int x0 = (h * NSPLITS + i) * SQ + j;
        const int x1 = (h * NSPLITS + i + 16) * SQ + j;
        const float2 v0 = __half22float2(
            *(const __half2*)&g_po[(size_t)x0 * HD + 2 * d2]);
        const float2 v1 = __half22float2(
            *(const __half2*)&g_po[(size_t)x1 * HD + 2 * d2]);
        L0 = fmaf(sl[i], f0, L0);
        ox0 = fmaf(f0, v0.x, ox0); oy0 = fmaf(f0, v0.y, oy0);
        L1 = fmaf(sl[i + 16], f1, L1);
        ox1 = fmaf(f1, v1.x, ox1); oy1 = fmaf(f1, v1.y, oy1);
    }
    for (; i < NSPLITS; i += 16) {
        const float f0 = sf[i];
        const int x0 = (h * NSPLITS + i) * SQ + j;
        const float2 v0 = __half22float2(
            *(const __half2*)&g_po[(size_t)x0 * HD + 2 * d2]);
        L0 = fmaf(sl[i], f0, L0);
        ox0 = fmaf(f0, v0.x, ox0); oy0 = fmaf(f0, v0.y, oy0);
    }
    sO[grp][d2] = make_float2(ox0 + ox1, oy0 + oy1);
    if (d2 == 0) sL[grp] = L0 + L1;
    __syncthreads();
    if (grp == 0) {
        float2 oo = sO[0][d2];
        float LL = sL[0];
        for (int u = 1; u < 16; u++) {
            oo.x += sO[u][d2].x;
            oo.y += sO[u][d2].y;
            LL += sL[u];
        }
        const float inv = 1.f / LL;
        *(float2*)&g_a[j * EMB + h * HD + 2 * d2] =
            make_float2(oo.x * inv, oo.y * inv);
    }
}

// ---------------------------------------------------------------------------
// Reduce proj partials + bias -> d_out[0 : 32*1024)  (MLP 4)
// ---------------------------------------------------------------------------
__global__ __launch_bounds__(256) void reduce_proj_kernel(
    const float* __restrict__ b, float* __restrict__ dout)
{
    const int c = blockIdx.x * 256 + threadIdx.x;   // 0..1023
    const int r = blockIdx.y;
    float v0 = b[c], v1 = 0.f, v2 = 0.f, v3 = 0.f;
#pragma unroll
    for (int kc = 0; kc < KCH; kc += 4) {
        v0 += g_pprj[((size_t)kc * SQ + r) * EMB + c];
        v1 += g_pprj[((size_t)(kc + 1) * SQ + r) * EMB + c];
        v2 += g_pprj[((size_t)(kc + 2) * SQ + r) * EMB + c];
        v3 += g_pprj[((size_t)(kc + 3) * SQ + r) * EMB + c];
    }
    dout[r * EMB + c] = (v0 + v1) + (v2 + v3);
}

// ---------------------------------------------------------------------------
extern "C" void kernel_launch(void* const* d_in, const int* in_sizes, int n_in,
                              void* d_out, int out_size)
{
    const float* x      = (const float*)d_in[0];
    const float* past   = (const float*)d_in[1];
    const float* w_attn = (const float*)d_in[2];
    const float* b_attn = (const float*)d_in[3];
    const float* w_proj = (const float*)d_in[4];
    const float* b_proj = (const float*)d_in[5];
    float* out = (float*)d_out;

    float* pqkv; cudaGetSymbolAddress((void**)&pqkv, g_pqkv);
    float* pprj; cudaGetSymbolAddress((void**)&pprj, g_pprj);
    float* ga;   cudaGetSymbolAddress((void**)&ga,   g_a);

    cudaFuncSetAttribute(attn_kernel,
                         cudaFuncAttributeMaxDynamicSharedMemorySize, 81920);

    gemm_part_kernel  <<<dim3(24, KCH), 128>>>(x, w_attn, pqkv, 3 * EMB);
    reduce_qkv_kernel <<<dim3(12, SQ),  256>>>(b_attn, out);
    attn_kernel       <<<dim3(NSPLITS, 4), 256, 81920>>>(past, out);
    combine_kernel    <<<dim3(NH, SQ),  512>>>();
    gemm_part_kernel  <<<dim3(8, KCH),  128>>>(ga, w_proj, pprj, EMB);
    reduce_proj_kernel<<<dim3(4, SQ),   256>>>(b_proj, out);
}

// round 17
// speedup vs baseline: 1.0310x; 1.0005x over previous
#include <cuda_runtime.h>
#include <cuda_fp16.h>

#define SQ      32
#define EMB     1024
#define NH      16
#define HD      64
#define PASTN   32768
#define TOT     32800
#define NSPLITS 74       // 73 past splits (28/29 tiles, balanced) + 1 new-token split
#define KCH     16
#define KCHLEN  64

// Scratch (allocation-free rule: __device__ globals)
__device__ float  g_qkv [SQ * 3 * EMB];
__device__ __half g_po  [NH * NSPLITS * SQ * HD];   // fp16 partial O
__device__ float  g_pml [NH * NSPLITS * SQ * 2];
__device__ float  g_a   [SQ * EMB];
__device__ float  g_pqkv[KCH * SQ * 3 * EMB];
__device__ float  g_pprj[KCH * SQ * EMB];

// ------------------------- helpers ----------------------------------------
__device__ __forceinline__ unsigned long long ffma2(
    unsigned long long a, unsigned long long b, unsigned long long c) {
    unsigned long long d;
    asm("fma.rn.f32x2 %0, %1, %2, %3;" : "=l"(d) : "l"(a), "l"(b), "l"(c));
    return d;
}
__device__ __forceinline__ unsigned long long pack2(float x, float y) {
    unsigned long long r;
    asm("mov.b64 %0, {%1, %2};" : "=l"(r) : "f"(x), "f"(y));
    return r;
}
__device__ __forceinline__ float2 unpack2(unsigned long long v) {
    float2 r;
    asm("mov.b64 {%0, %1}, %2;" : "=f"(r.x), "=f"(r.y) : "l"(v));
    return r;
}
__device__ __forceinline__ float ex2(float x) {
    float r;
    asm("ex2.approx.f32 %0, %1;" : "=f"(r) : "f"(x));
    return r;
}
__device__ __forceinline__ unsigned f2tf(float f) {
    unsigned u;
    asm("cvt.rna.tf32.f32 %0, %1;" : "=r"(u) : "f"(f));
    return u;
}
__device__ __forceinline__ void cp16(unsigned int saddr, const void* gptr) {
    asm volatile("cp.async.cg.shared.global [%0], [%1], 16;"
                 :: "r"(saddr), "l"(gptr));
}
__device__ __forceinline__ void mma_tf32(
    float* d, const unsigned* a, unsigned b0, unsigned b1) {
    asm volatile(
        "mma.sync.aligned.m16n8k8.row.col.f32.tf32.tf32.f32 "
        "{%0,%1,%2,%3}, {%4,%5,%6,%7}, {%8,%9}, {%0,%1,%2,%3};"
        : "+f"(d[0]), "+f"(d[1]), "+f"(d[2]), "+f"(d[3])
        : "r"(a[0]), "r"(a[1]), "r"(a[2]), "r"(a[3]), "r"(b0), "r"(b1));
}

// ---------------------------------------------------------------------------
// Split-K GEMM partial: part[kc][r][C] = x[r][k0:k0+64] @ w[k0:k0+64][C]
// (+ bias when kc == 0). grid (C/128, KCH), block 128.
// ---------------------------------------------------------------------------
__global__ __launch_bounds__(128) void gemm_part_kernel(
    const float* __restrict__ xsrc, const float* __restrict__ w,
    const float* __restrict__ b, float* __restrict__ part, int C)
{
    __shared__ float xs_t[KCHLEN][36];
    const int c  = blockIdx.x * 128 + threadIdx.x;
    const int k0 = blockIdx.y * KCHLEN;

    {
        const int k = threadIdx.x & 63;
        const int j0 = (threadIdx.x >> 6) * 16;
#pragma unroll
        for (int jj = 0; jj < 16; jj++)
            xs_t[k][j0 + jj] = xsrc[(j0 + jj) * EMB + k0 + k];
    }
    __syncthreads();

    unsigned long long acc[16];
    {
        const float bv = (blockIdx.y == 0) ? b[c] : 0.f;
        const unsigned long long b2 = pack2(bv, bv);
        acc[0] = b2;
#pragma unroll
        for (int i = 1; i < 16; i++) acc[i] = 0ull;
        // note: bias added to acc[0] covers rows 0,1 only — wrong; instead
        // fold bias into every row by adding after the loop (see below).
        acc[0] = 0ull;
        (void)b2;
    }

#pragma unroll 16
    for (int k = 0; k < KCHLEN; k++) {
        const float wv = w[(size_t)(k0 + k) * C + c];
        const unsigned long long w2 = pack2(wv, wv);
#pragma unroll
        for (int r4 = 0; r4 < 8; r4++) {
            const ulonglong2 x4 = *(const ulonglong2*)&xs_t[k][r4 * 4];
            acc[r4 * 2]     = ffma2(x4.x, w2, acc[r4 * 2]);
            acc[r4 * 2 + 1] = ffma2(x4.y, w2, acc[r4 * 2 + 1]);
        }
    }

    const float bv = (blockIdx.y == 0) ? b[c] : 0.f;
    float* p = part + (size_t)blockIdx.y * SQ * C + c;
#pragma unroll
    for (int i = 0; i < 16; i++) {
        const float2 v = unpack2(acc[i]);
        p[(size_t)(2 * i)     * C] = v.x + bv;
        p[(size_t)(2 * i + 1) * C] = v.y + bv;
    }
}

// ---------------------------------------------------------------------------
// Reduce qkv partials -> g_qkv ; scatter new K/V rows into present tail
// ---------------------------------------------------------------------------
__global__ __launch_bounds__(256) void reduce_qkv_kernel(float* __restrict__ dout)
{
    const int c = blockIdx.x * 256 + threadIdx.x;   // 0..3071
    const int r = blockIdx.y;
    float v0 = 0.f, v1 = 0.f, v2 = 0.f, v3 = 0.f;
#pragma unroll
    for (int kc = 0; kc < KCH; kc += 4) {
        v0 += g_pqkv[((size_t)kc * SQ + r) * (3 * EMB) + c];
        v1 += g_pqkv[((size_t)(kc + 1) * SQ + r) * (3 * EMB) + c];
        v2 += g_pqkv[((size_t)(kc + 2) * SQ + r) * (3 * EMB) + c];
        v3 += g_pqkv[((size_t)(kc + 3) * SQ + r) * (3 * EMB) + c];
    }
    const float v = (v0 + v1) + (v2 + v3);
    g_qkv[r * 3 * EMB + c] = v;
    if (c >= EMB) {
        const int which = (c >= 2 * EMB) ? 1 : 0;   // 0=K, 1=V
        const int cc = c - EMB - which * EMB;
        const int h = cc / HD, d = cc % HD;
        dout[(size_t)SQ * EMB
             + ((size_t)which * NH + h) * (size_t)TOT * HD
             + (size_t)(PASTN + r) * HD + d] = v;
    }
}

// ---------------------------------------------------------------------------
// Attention via mma.sync tf32. CTA = 256 thr = 8 warps = 4 heads x 2 q-halves.
// grid (NSPLITS, 4) = 296 CTAs = 1 wave. Balanced splits: 69x28 + 4x29 tiles.
// Per-pair named barriers. SAFE pipeline:
//   wait_group 0 -> pair-bar -> prefetch(i+1) -> compute.
// smem: K[4][2][16][68] + V[4][2][16][72] + Ps[8][16][20] = 80 KB.
// ---------------------------------------------------------------------------
#define KPAD 68
#define VPAD 72
#define K_OFF(head, buf) ((head) * 2176 + (buf) * 1088)
#define V_OFF(head, buf) (8704 + (head) * 2304 + (buf) * 1152)
#define P_OFF(warpid)    (17920 + (warpid) * 320)

__global__ __launch_bounds__(256) void attn_kernel(
    const float* __restrict__ past, float* __restrict__ dout)
{
    extern __shared__ float smem[];
    const int warp = threadIdx.x >> 5, lane = threadIdx.x & 31;
    const int head = warp >> 1, whalf = warp & 1;
    const int g = lane >> 2, t = lane & 3;
    const int sp = blockIdx.x;
    const int h  = blockIdx.y * 4 + head;

    const bool isnew = (sp == NSPLITS - 1);
    int t0, nt;
    if (isnew) { t0 = PASTN; nt = (TOT - PASTN) >> 4; }
    else {       // balanced tiling: 2048 tiles over 73 splits = 69x28 + 4x29
        const int st = sp * 28 + min(sp, 4);
        t0 = st << 4;
        nt = 28 + (sp < 4 ? 1 : 0);
    }

    // ---- Q fragments: 8 k-steps x 4 regs (rows qlo=whalf*16+g, qhi=+8) ----
    const int qlo = whalf * 16 + g, qhi = qlo + 8;
    const float qc = 0.125f * 1.4426950408889634f;   // 1/sqrt(d) * log2(e)
    unsigned qf[32];
    {
        const float* qL = g_qkv + qlo * 3 * EMB + h * HD;
        const float* qH = g_qkv + qhi * 3 * EMB + h * HD;
#pragma unroll
        for (int ks = 0; ks < 8; ks++) {
            qf[ks * 4 + 0] = f2tf(qL[ks * 8 + t]     * qc);
            qf[ks * 4 + 1] = f2tf(qH[ks * 8 + t]     * qc);
            qf[ks * 4 + 2] = f2tf(qL[ks * 8 + t + 4] * qc);
            qf[ks * 4 + 3] = f2tf(qH[ks * 8 + t + 4] * qc);
        }
    }

    float of[8][4];
#pragma unroll
    for (int n = 0; n < 8; n++)
#pragma unroll
        for (int r = 0; r < 4; r++) of[n][r] = 0.f;
    float mlo = -1e30f, mhi = -1e30f, llo = 0.f, lhi = 0.f;

    float* presK = dout + SQ * EMB + (size_t)h * TOT * HD;
    float* presV = presK + (size_t)NH * TOT * HD;
    const float* srcK = isnew ? (presK + (size_t)t0 * HD)
                              : (past + ((size_t)h * PASTN + t0) * (size_t)HD);
    const float* srcV = isnew ? (presV + (size_t)t0 * HD)
                              : (past + ((size_t)(NH + h) * PASTN + t0) * (size_t)HD);

    float* Ps = smem + P_OFF(warp);
    unsigned* Pu = (unsigned*)Ps;
    const unsigned KsA = (unsigned)__cvta_generic_to_shared(smem);

    // ---- prefetch tile 0 (this warp loads its half of the head's rows) ----
#pragma unroll
    for (int r = 0; r < 4; r++) {
        const int idx = whalf * 128 + r * 32 + lane;   // 0..255 over pair
        const int row = idx >> 4, c4 = idx & 15;
        cp16(KsA + (unsigned)(K_OFF(head, 0) + row * KPAD + c4 * 4) * 4u,
             srcK + row * HD + c4 * 4);
        cp16(KsA + (unsigned)(V_OFF(head, 0) + row * VPAD + c4 * 4) * 4u,
             srcV + row * HD + c4 * 4);
    }
    asm volatile("cp.async.commit_group;");

    for (int i = 0; i < nt; i++) {
        const int buf = i & 1;
        // Tile i (K and V, this warp's halves) landed.
        asm volatile("cp.async.wait_group 0;");
        // Pair barrier: partner's halves also landed (its wait precedes its
        // barrier arrival), and partner finished compute i-1 -> the buffer
        // we prefetch into below is free.
        asm volatile("bar.sync %0, 64;" :: "r"(head + 1));

        if (i + 1 < nt) {
            const size_t gb = (size_t)(i + 1) * 16 * HD;
            const int bo = buf ^ 1;
#pragma unroll
            for (int r = 0; r < 4; r++) {
                const int idx = whalf * 128 + r * 32 + lane;
                const int row = idx >> 4, c4 = idx & 15;
                cp16(KsA + (unsigned)(K_OFF(head, bo) + row * KPAD + c4 * 4) * 4u,
                     srcK + gb + row * HD + c4 * 4);
                cp16(KsA + (unsigned)(V_OFF(head, bo) + row * VPAD + c4 * 4) * 4u,
                     srcV + gb + row * HD + c4 * 4);
            }
            asm volatile("cp.async.commit_group;");
        }

        const float* Kt = smem + K_OFF(head, buf);
        const float* Vt = smem + V_OFF(head, buf);
        const unsigned* Ku = (const unsigned*)Kt;
        const unsigned* Vu = (const unsigned*)Vt;
        const int tt = t0 + i * 16;

        // ---- QK: 2 n-tiles x 8 k-steps (2 acc chains each) ----
        float s[2][4];
#pragma unroll
        for (int n = 0; n < 2; n++) {
            float ca[4] = {0.f, 0.f, 0.f, 0.f};
            float cb[4] = {0.f, 0.f, 0.f, 0.f};
            const unsigned* Kr = Ku + (n * 8 + g) * KPAD + t;
#pragma unroll
            for (int ks = 0; ks < 4; ks++) {
                mma_tf32(ca, qf + 4 * ks,       Kr[ks * 8],       Kr[ks * 8 + 4]);
                mma_tf32(cb, qf + 4 * (ks + 4), Kr[(ks + 4) * 8], Kr[(ks + 4) * 8 + 4]);
            }
#pragma unroll
            for (int r = 0; r < 4; r++) s[n][r] = ca[r] + cb[r];
        }

        // ---- K copy-through (streaming stores; data landed pre-barrier) ----
        if (!isnew) {
#pragma unroll
            for (int r = 0; r < 4; r++) {
                const int idx = whalf * 128 + r * 32 + lane;
                const int row = idx >> 4, c4 = idx & 15;
                __stcs((float4*)&presK[(size_t)(tt + row) * HD + c4 * 4],
                       *(const float4*)(Kt + row * KPAD + c4 * 4));
            }
        }

        // ---- causal mask (new-token split only) ----
        if (isnew) {
            const int kb = i * 16;
#pragma unroll
            for (int n = 0; n < 2; n++) {
                const int col = n * 8 + 2 * t;
                if (kb + col     > qlo) s[n][0] = -1e30f;
                if (kb + col + 1 > qlo) s[n][1] = -1e30f;
                if (kb + col     > qhi) s[n][2] = -1e30f;
                if (kb + col + 1 > qhi) s[n][3] = -1e30f;
            }
        }

        // ---- online softmax (quad shfl reductions) ----
        float vlo = fmaxf(fmaxf(s[0][0], s[0][1]), fmaxf(s[1][0], s[1][1]));
        float vhi = fmaxf(fmaxf(s[0][2], s[0][3]), fmaxf(s[1][2], s[1][3]));
        vlo = fmaxf(vlo, __shfl_xor_sync(0xffffffffu, vlo, 1));
        vlo = fmaxf(vlo, __shfl_xor_sync(0xffffffffu, vlo, 2));
        vhi = fmaxf(vhi, __shfl_xor_sync(0xffffffffu, vhi, 1));
        vhi = fmaxf(vhi, __shfl_xor_sync(0xffffffffu, vhi, 2));
        const float nmlo = fmaxf(mlo, vlo), nmhi = fmaxf(mhi, vhi);
        const float allo = ex2(mlo - nmlo), alhi = ex2(mhi - nmhi);
        mlo = nmlo; mhi = nmhi;

        float p[2][4];
#pragma unroll
        for (int n = 0; n < 2; n++) {
            p[n][0] = ex2(s[n][0] - nmlo);
            p[n][1] = ex2(s[n][1] - nmlo);
            p[n][2] = ex2(s[n][2] - nmhi);
            p[n][3] = ex2(s[n][3] - nmhi);
        }
        float slo = (p[0][0] + p[0][1]) + (p[1][0] + p[1][1]);
        float shi = (p[0][2] + p[0][3]) + (p[1][2] + p[1][3]);
        slo += __shfl_xor_sync(0xffffffffu, slo, 1);
        slo += __shfl_xor_sync(0xffffffffu, slo, 2);
        shi += __shfl_xor_sync(0xffffffffu, shi, 1);
        shi += __shfl_xor_sync(0xffffffffu, shi, 2);
        llo = llo * allo + slo;
        lhi = lhi * alhi + shi;

#pragma unroll
        for (int n = 0; n < 8; n++) {
            of[n][0] *= allo; of[n][1] *= allo;
            of[n][2] *= alhi; of[n][3] *= alhi;
        }

        // ---- P -> smem pre-converted to tf32 (CVTs off the PV path) ----
#pragma unroll
        for (int n = 0; n < 2; n++) {
            *(uint2*)&Pu[g * 20 + n * 8 + 2 * t] =
                make_uint2(f2tf(p[n][0]), f2tf(p[n][1]));
            *(uint2*)&Pu[(g + 8) * 20 + n * 8 + 2 * t] =
                make_uint2(f2tf(p[n][2]), f2tf(p[n][3]));
        }
        __syncwarp();

        // ---- PV: 2 k-steps x 8 n-tiles ----
#pragma unroll
        for (int ks = 0; ks < 2; ks++) {
            unsigned pa[4];
            pa[0] = Pu[g * 20 + ks * 8 + t];
            pa[1] = Pu[(g + 8) * 20 + ks * 8 + t];
            pa[2] = Pu[g * 20 + ks * 8 + t + 4];
            pa[3] = Pu[(g + 8) * 20 + ks * 8 + t + 4];
            const unsigned* V0 = Vu + (ks * 8 + t) * VPAD + g;
            const unsigned* V1 = Vu + (ks * 8 + t + 4) * VPAD + g;
#pragma unroll
            for (int n = 0; n < 8; n++)
                mma_tf32(of[n], pa, V0[n * 8], V1[n * 8]);
        }

        // ---- V copy-through (streaming stores) ----
        if (!isnew) {
#pragma unroll
            for (int r = 0; r < 4; r++) {
                const int idx = whalf * 128 + r * 32 + lane;
                const int row = idx >> 4, c4 = idx & 15;
                __stcs((float4*)&presV[(size_t)(tt + row) * HD + c4 * 4],
                       *(const float4*)(Vt + row * VPAD + c4 * 4));
            }
        }
        // (no trailing __syncwarp: next iteration's bar.sync orders the
        //  Ps write-after-read hazard)
    }

    // ---- epilogue: fp16 partial O ----
    const int pbl = (h * NSPLITS + sp) * SQ + qlo;
    const int pbh = (h * NSPLITS + sp) * SQ + qhi;
#pragma unroll
    for (int n = 0; n < 8; n++) {
        *(__half2*)&g_po[(size_t)pbl * HD + n * 8 + 2 * t] =
            __floats2half2_rn(of[n][0], of[n][1]);
        *(__half2*)&g_po[(size_t)pbh * HD + n * 8 + 2 * t] =
            __floats2half2_rn(of[n][2], of[n][3]);
    }
    if (t == 0) {
        g_pml[pbl * 2] = mlo; g_pml[pbl * 2 + 1] = llo;
        g_pml[pbh * 2] = mhi; g_pml[pbh * 2 + 1] = lhi;
    }
}

// ---------------------------------------------------------------------------
// Combine split partials -> g_a. grid (NH, SQ), 512 threads:
// 16 split-groups x 32 dim-pairs; half2 loads, FOUR independent load chains
// (combine is L2-latency-bound: g_po lives in L2 after attn).
// ---------------------------------------------------------------------------
__global__ __launch_bounds__(512) void combine_kernel()
{
    const int h = blockIdx.x, j = blockIdx.y;
    const int d2  = threadIdx.x & 31;        // dim pair: dims 2*d2, 2*d2+1
    const int grp = threadIdx.x >> 5;        // 0..15
    __shared__ float  sf[NSPLITS], sl[NSPLITS];
    __shared__ float2 sO[16][32];
    __shared__ float  sL[16];

    for (int i = threadIdx.x; i < NSPLITS; i += 512) {
        const float2 ml = *(const float2*)&g_pml[((h * NSPLITS + i) * SQ + j) * 2];
        sf[i] = ml.x;
        sl[i] = ml.y;
    }
    __syncthreads();

    float gm = -1e30f;
    for (int i = 0; i < NSPLITS; i++) gm = fmaxf(gm, sf[i]);
    __syncthreads();
    for (int i = threadIdx.x; i < NSPLITS; i += 512)
        sf[i] = ex2(sf[i] - gm);
    __syncthreads();

    float L[4]  = {0.f, 0.f, 0.f, 0.f};
    float ox[4] = {0.f, 0.f, 0.f, 0.f};
    float oy[4] = {0.f, 0.f, 0.f, 0.f};
    int i = grp;
    for (; i + 48 < NSPLITS; i += 64) {
#pragma unroll
        for (int u = 0; u < 4; u++) {
            const int ii = i + 16 * u;
            const float f = sf[ii];
            const int x = (h * NSPLITS + ii) * SQ + j;
            const float2 v = __half22float2(
                *(const __half2*)&g_po[(size_t)x * HD + 2 * d2]);
            L[u]  = fmaf(sl[ii], f, L[u]);
            ox[u] = fmaf(f, v.x, ox[u]);
            oy[u] = fmaf(f, v.y, oy[u]);
        }
    }
    for (; i < NSPLITS; i += 16) {
        const float f = sf[i];
        const int x = (h * NSPLITS + i) * SQ + j;
        const float2 v = __half22float2(
            *(const __half2*)&g_po[(size_t)x * HD + 2 * d2]);
        L[0]  = fmaf(sl[i], f, L[0]);
        ox[0] = fmaf(f, v.x, ox[0]);
        oy[0] = fmaf(f, v.y, oy[0]);
    }
    sO[grp][d2] = make_float2((ox[0] + ox[1]) + (ox[2] + ox[3]),
                              (oy[0] + oy[1]) + (oy[2] + oy[3]));
    if (d2 == 0) sL[grp] = (L[0] + L[1]) + (L[2] + L[3]);
    __syncthreads();
    if (grp == 0) {
        float2 oo = sO[0][d2];
        float LL = sL[0];
        for (int u = 1; u < 16; u++) {
            oo.x += sO[u][d2].x;
            oo.y += sO[u][d2].y;
            LL += sL[u];
        }
        const float inv = 1.f / LL;
        *(float2*)&g_a[j * EMB + h * HD + 2 * d2] =
            make_float2(oo.x * inv, oo.y * inv);
    }
}

// ---------------------------------------------------------------------------
// Reduce proj partials -> d_out[0 : 32*1024)  (bias already folded, MLP 4)
// ---------------------------------------------------------------------------
__global__ __launch_bounds__(256) void reduce_proj_kernel(float* __restrict__ dout)
{
    const int c = blockIdx.x * 256 + threadIdx.x;   // 0..1023
    const int r = blockIdx.y;
    float v0 = 0.f, v1 = 0.f, v2 = 0.f, v3 = 0.f;
#pragma unroll
    for (int kc = 0; kc < KCH; kc += 4) {
        v0 += g_pprj[((size_t)kc * SQ + r) * EMB + c];
        v1 += g_pprj[((size_t)(kc + 1) * SQ + r) * EMB + c];
        v2 += g_pprj[((size_t)(kc + 2) * SQ + r) * EMB + c];
        v3 += g_pprj[((size_t)(kc + 3) * SQ + r) * EMB + c];
    }
    dout[r * EMB + c] = (v0 + v1) + (v2 + v3);
}

// ---------------------------------------------------------------------------
extern "C" void kernel_launch(void* const* d_in, const int* in_sizes, int n_in,
                              void* d_out, int out_size)
{
    const float* x      = (const float*)d_in[0];
    const float* past   = (const float*)d_in[1];
    const float* w_attn = (const float*)d_in[2];
    const float* b_attn = (const float*)d_in[3];
    const float* w_proj = (const float*)d_in[4];
    const float* b_proj = (const float*)d_in[5];
    float* out = (float*)d_out;

    float* pqkv; cudaGetSymbolAddress((void**)&pqkv, g_pqkv);
    float* pprj; cudaGetSymbolAddress((void**)&pprj, g_pprj);
    float* ga;   cudaGetSymbolAddress((void**)&ga,   g_a);

    cudaFuncSetAttribute(attn_kernel,
                         cudaFuncAttributeMaxDynamicSharedMemorySize, 81920);

    gemm_part_kernel  <<<dim3(24, KCH), 128>>>(x, w_attn, b_attn, pqkv, 3 * EMB);
    reduce_qkv_kernel <<<dim3(12, SQ),  256>>>(out);
    attn_kernel       <<<dim3(NSPLITS, 4), 256, 81920>>>(past, out);
    combine_kernel    <<<dim3(NH, SQ),  512>>>();
    gemm_part_kernel  <<<dim3(8, KCH),  128>>>(ga, w_proj, b_proj, pprj, EMB);
    reduce_proj_kernel<<<dim3(4, SQ),   256>>>(out);
}